// round 3
// baseline (speedup 1.0000x reference)
#include <cuda_runtime.h>
#include <cuda_bf16.h>
#include <math.h>
#include <stdint.h>

// Problem dims (fixed for this problem)
#define Vv 32000
#define Dd 1024
#define Bb 8
#define Tt 256
#define Mrows (Bb * Tt)   // 2048

// ---------------- scratch (static device globals; allocation-free) ----------
__device__ __nv_bfloat16 g_Xb[Mrows * Dd];        // gathered embeddings, bf16
__device__ __nv_bfloat16 g_Wb[Dd * Dd];           // W in bf16
__device__ __nv_bfloat16 g_Woutb[(size_t)Vv * Dd];// Wout in bf16 (~65.5 MB)
__device__ float g_Wx[Mrows * Dd];                // input projection result
__device__ __nv_bfloat16 g_hsb[Mrows * Dd];       // hidden states, bf16
__device__ float g_h[2][Bb * Dd];                 // h ping-pong
__device__ float g_lse[Mrows];

// grid barrier state
__device__ unsigned g_bar_count;
__device__ volatile unsigned g_bar_gen;

// ---------------- small helpers --------------------------------------------
__global__ void f32_to_bf16_kernel(const float4* __restrict__ src,
                                   __nv_bfloat162* __restrict__ dst, int n4) {
    for (int i = blockIdx.x * blockDim.x + threadIdx.x; i < n4;
         i += gridDim.x * blockDim.x) {
        float4 v = src[i];
        dst[2 * i]     = __floats2bfloat162_rn(v.x, v.y);
        dst[2 * i + 1] = __floats2bfloat162_rn(v.z, v.w);
    }
}

__global__ void gather_embed_kernel(const int* __restrict__ idx,
                                    const float* __restrict__ E,
                                    __nv_bfloat16* __restrict__ Xb) {
    int row = blockIdx.x;                 // row = b*T + t
    int v = idx[row];
    const float4* src = (const float4*)(E + (size_t)v * Dd);
    __nv_bfloat162* dst = (__nv_bfloat162*)(Xb + (size_t)row * Dd);
    for (int i = threadIdx.x; i < Dd / 4; i += blockDim.x) {
        float4 a = src[i];
        dst[2 * i]     = __floats2bfloat162_rn(a.x, a.y);
        dst[2 * i + 1] = __floats2bfloat162_rn(a.z, a.w);
    }
}

// ---------------- bf16 MMA GEMM:  C[M,N] = A[M,K] * B[N,K]^T + bias[N] ------
// BM=128, BN=128, BK=32, 256 threads, 8 warps as 2(m) x 4(n), warp tile 64x32.
__device__ __forceinline__ void mma16816(float& c0, float& c1, float& c2, float& c3,
                                         uint32_t a0, uint32_t a1, uint32_t a2, uint32_t a3,
                                         uint32_t b0, uint32_t b1) {
    asm volatile(
        "mma.sync.aligned.m16n8k16.row.col.f32.bf16.bf16.f32 "
        "{%0,%1,%2,%3}, {%4,%5,%6,%7}, {%8,%9}, {%0,%1,%2,%3};\n"
        : "+f"(c0), "+f"(c1), "+f"(c2), "+f"(c3)
        : "r"(a0), "r"(a1), "r"(a2), "r"(a3), "r"(b0), "r"(b1));
}

__global__ __launch_bounds__(256)
void gemm_bf16_kernel(const __nv_bfloat16* __restrict__ A,
                      const __nv_bfloat16* __restrict__ Bm,
                      const float* __restrict__ bias,
                      float* __restrict__ C,
                      int M, int N, int K) {
    __shared__ __nv_bfloat16 As[128][40];   // BK=32 + 8 pad, 16B-aligned rows
    __shared__ __nv_bfloat16 Bs[128][40];

    const int bm = blockIdx.x, bn = blockIdx.y;
    const int tid = threadIdx.x;
    const int warp = tid >> 5, lane = tid & 31;
    const int wm = warp >> 2, wn = warp & 3;      // 2 x 4 warp grid
    const int g = lane >> 2, tq = lane & 3;

    float acc[4][4][4];
#pragma unroll
    for (int mi = 0; mi < 4; mi++)
#pragma unroll
        for (int ni = 0; ni < 4; ni++)
#pragma unroll
            for (int q = 0; q < 4; q++) acc[mi][ni][q] = 0.f;

    const __nv_bfloat16* Ag = A + (size_t)(bm * 128) * K;
    const __nv_bfloat16* Bg = Bm + (size_t)(bn * 128) * K;

    for (int kt = 0; kt < K; kt += 32) {
#pragma unroll
        for (int j = 0; j < 2; j++) {
            int id = tid + j * 256;               // 0..511
            int row = id >> 2, seg = id & 3;
            *(uint4*)&As[row][seg * 8] =
                *(const uint4*)(Ag + (size_t)row * K + kt + seg * 8);
            *(uint4*)&Bs[row][seg * 8] =
                *(const uint4*)(Bg + (size_t)row * K + kt + seg * 8);
        }
        __syncthreads();

#pragma unroll
        for (int ks = 0; ks < 32; ks += 16) {
            uint32_t af[4][4], bf[4][2];
#pragma unroll
            for (int mi = 0; mi < 4; mi++) {
                int r = wm * 64 + mi * 16 + g;
                af[mi][0] = *(const uint32_t*)&As[r][ks + tq * 2];
                af[mi][1] = *(const uint32_t*)&As[r + 8][ks + tq * 2];
                af[mi][2] = *(const uint32_t*)&As[r][ks + tq * 2 + 8];
                af[mi][3] = *(const uint32_t*)&As[r + 8][ks + tq * 2 + 8];
            }
#pragma unroll
            for (int ni = 0; ni < 4; ni++) {
                int c = wn * 32 + ni * 8 + g;
                bf[ni][0] = *(const uint32_t*)&Bs[c][ks + tq * 2];
                bf[ni][1] = *(const uint32_t*)&Bs[c][ks + tq * 2 + 8];
            }
#pragma unroll
            for (int mi = 0; mi < 4; mi++)
#pragma unroll
                for (int ni = 0; ni < 4; ni++)
                    mma16816(acc[mi][ni][0], acc[mi][ni][1],
                             acc[mi][ni][2], acc[mi][ni][3],
                             af[mi][0], af[mi][1], af[mi][2], af[mi][3],
                             bf[ni][0], bf[ni][1]);
        }
        __syncthreads();
    }

    // epilogue: + bias, float2 stores
#pragma unroll
    for (int ni = 0; ni < 4; ni++) {
        int col = bn * 128 + wn * 32 + ni * 8 + tq * 2;
        float b0 = bias[col], b1 = bias[col + 1];
#pragma unroll
        for (int mi = 0; mi < 4; mi++) {
            int row = bm * 128 + wm * 64 + mi * 16 + g;
            *(float2*)&C[(size_t)row * N + col] =
                make_float2(acc[mi][ni][0] + b0, acc[mi][ni][1] + b1);
            *(float2*)&C[(size_t)(row + 8) * N + col] =
                make_float2(acc[mi][ni][2] + b0, acc[mi][ni][3] + b1);
        }
    }
}

// ---------------- persistent RNN recurrence ---------------------------------
// 128 CTAs x 128 threads. CTA owns 8 rows of U (SMEM-resident). Per step:
// stage h (L2->SMEM, .cg), 4 warps x 2 rows x 8 batch, lane-strided K,
// butterfly-reduce, tanh, write h ping-pong + hs bf16, grid barrier.
#define RNN_BLOCKS 128
#define RNN_THREADS 128
#define PADROW 1028                       // 1024 + 4 floats pad (16B aligned)
#define RNN_SMEM (2 * 8 * PADROW * 4)     // U slice + h stage

__device__ __forceinline__ void grid_bar() {
    __syncthreads();
    if (threadIdx.x == 0) {
        unsigned gen = g_bar_gen;
        __threadfence();
        unsigned t = atomicAdd(&g_bar_count, 1u);
        if (t == RNN_BLOCKS - 1) {
            atomicExch(&g_bar_count, 0u);
            __threadfence();
            g_bar_gen = gen + 1;
        } else {
            while (g_bar_gen == gen) { }
        }
    }
    __syncthreads();
}

__global__ __launch_bounds__(RNN_THREADS)
void rnn_recurrence_kernel(const float* __restrict__ Wx,
                           const float* __restrict__ U,
                           const float* __restrict__ bU,
                           __nv_bfloat16* __restrict__ hsb) {
    extern __shared__ float sm[];
    float* Usm = sm;                 // [8][PADROW]
    float* hsm = sm + 8 * PADROW;    // [8][PADROW]  (h transposed-by-batch rows)

    const int tid = threadIdx.x;
    const int lane = tid & 31, w = tid >> 5;   // 4 warps
    const int rb = blockIdx.x * 8;             // first global U row of this CTA

    // load U slice (8 rows x 1024) into padded SMEM
    for (int i = tid; i < 8 * 256; i += RNN_THREADS) {
        int lr = i >> 8, kc = i & 255;
        float4 u = *(const float4*)(U + (size_t)(rb + lr) * Dd + kc * 4);
        *(float4*)&Usm[lr * PADROW + kc * 4] = u;
    }

    // zero h0 (buffer 0) cooperatively
    int gid = blockIdx.x * RNN_THREADS + tid;
    if (gid < Bb * Dd) __stcg(&g_h[0][gid], 0.f);
    grid_bar();

    for (int t = 0; t < Tt; t++) {
        const float* hc = g_h[t & 1];
        // stage h: 8 x 1024 floats, bypass L1 (written by other SMs)
        for (int i = tid; i < 2048; i += RNN_THREADS) {
            float4 v = __ldcg((const float4*)hc + i);
            int b = i >> 8, kc = i & 255;
            *(float4*)&hsm[b * PADROW + kc * 4] = v;
        }
        __syncthreads();

        float acc[2][8];
#pragma unroll
        for (int r = 0; r < 2; r++)
#pragma unroll
            for (int b = 0; b < 8; b++) acc[r][b] = 0.f;

#pragma unroll
        for (int i = 0; i < 8; i++) {
            int k0 = lane * 4 + i * 128;
            float4 u0 = *(const float4*)&Usm[(w * 2) * PADROW + k0];
            float4 u1 = *(const float4*)&Usm[(w * 2 + 1) * PADROW + k0];
#pragma unroll
            for (int b = 0; b < 8; b++) {
                float4 h4 = *(const float4*)&hsm[b * PADROW + k0];
                acc[0][b] += u0.x * h4.x + u0.y * h4.y + u0.z * h4.z + u0.w * h4.w;
                acc[1][b] += u1.x * h4.x + u1.y * h4.y + u1.z * h4.z + u1.w * h4.w;
            }
        }

        // butterfly reductions: output j (=rr*8+b) ends on lane j
        float myval = 0.f;
#pragma unroll
        for (int j = 0; j < 16; j++) {
            float v = acc[j >> 3][j & 7];
            v += __shfl_xor_sync(0xffffffffu, v, 16);
            v += __shfl_xor_sync(0xffffffffu, v, 8);
            v += __shfl_xor_sync(0xffffffffu, v, 4);
            v += __shfl_xor_sync(0xffffffffu, v, 2);
            v += __shfl_xor_sync(0xffffffffu, v, 1);
            if (lane == j) myval = v;
        }

        if (lane < 16) {
            int rr = lane >> 3, b = lane & 7;
            int row = rb + w * 2 + rr;
            size_t wxi = ((size_t)b * Tt + t) * Dd + row;
            float x = myval + Wx[wxi] + bU[row];
            float hn = tanhf(x);
            __stcg(&g_h[(t & 1) ^ 1][b * Dd + row], hn);
            hsb[wxi] = __float2bfloat16(hn);
        }
        grid_bar();
    }
}

// ---------------- log-softmax epilogue --------------------------------------
__global__ __launch_bounds__(256)
void lse_kernel(const float* __restrict__ C, float* __restrict__ lse) {
    __shared__ float red[256];
    const int row = blockIdx.x, tid = threadIdx.x;
    const float4* p4 = (const float4*)(C + (size_t)row * Vv);

    float m = -1e30f;
    for (int i = tid; i < Vv / 4; i += 256) {
        float4 v = p4[i];
        m = fmaxf(m, fmaxf(fmaxf(v.x, v.y), fmaxf(v.z, v.w)));
    }
    red[tid] = m; __syncthreads();
    for (int s = 128; s > 0; s >>= 1) {
        if (tid < s) red[tid] = fmaxf(red[tid], red[tid + s]);
        __syncthreads();
    }
    m = red[0]; __syncthreads();

    float sum = 0.f;
    for (int i = tid; i < Vv / 4; i += 256) {
        float4 v = p4[i];
        sum += expf(v.x - m) + expf(v.y - m) + expf(v.z - m) + expf(v.w - m);
    }
    red[tid] = sum; __syncthreads();
    for (int s = 128; s > 0; s >>= 1) {
        if (tid < s) red[tid] += red[tid + s];
        __syncthreads();
    }
    if (tid == 0) lse[row] = m + logf(red[0]);
}

__global__ void sub_lse_kernel(float* __restrict__ C,
                               const float* __restrict__ lse, int total4) {
    for (int i = blockIdx.x * blockDim.x + threadIdx.x; i < total4;
         i += gridDim.x * blockDim.x) {
        float4 v = ((const float4*)C)[i];
        float l = __ldg(&lse[i / (Vv / 4)]);
        v.x -= l; v.y -= l; v.z -= l; v.w -= l;
        ((float4*)C)[i] = v;
    }
}

// ---------------- launcher ---------------------------------------------------
extern "C" void kernel_launch(void* const* d_in, const int* in_sizes, int n_in,
                              void* d_out, int out_size) {
    const int*   idx  = (const int*)d_in[0];
    const float* E    = (const float*)d_in[1];
    const float* W    = (const float*)d_in[2];
    const float* bW   = (const float*)d_in[3];
    const float* U    = (const float*)d_in[4];
    const float* bU   = (const float*)d_in[5];
    const float* Wout = (const float*)d_in[6];
    const float* bout = (const float*)d_in[7];
    float* out = (float*)d_out;

    void* p;
    cudaGetSymbolAddress(&p, g_Xb);    __nv_bfloat16* Xb    = (__nv_bfloat16*)p;
    cudaGetSymbolAddress(&p, g_Wb);    __nv_bfloat16* Wb    = (__nv_bfloat16*)p;
    cudaGetSymbolAddress(&p, g_Woutb); __nv_bfloat16* Woutb = (__nv_bfloat16*)p;
    cudaGetSymbolAddress(&p, g_Wx);    float*         Wx    = (float*)p;
    cudaGetSymbolAddress(&p, g_hsb);   __nv_bfloat16* hsb   = (__nv_bfloat16*)p;
    cudaGetSymbolAddress(&p, g_lse);   float*         lse   = (float*)p;

    cudaFuncSetAttribute(rnn_recurrence_kernel,
                         cudaFuncAttributeMaxDynamicSharedMemorySize, RNN_SMEM);

    // weight conversions
    f32_to_bf16_kernel<<<512, 256>>>((const float4*)W,
                                     (__nv_bfloat162*)Wb, (Dd * Dd) / 4);
    f32_to_bf16_kernel<<<4096, 256>>>((const float4*)Wout,
                                      (__nv_bfloat162*)Woutb, (Vv * Dd) / 4);
    // embedding gather -> bf16
    gather_embed_kernel<<<Mrows, 128>>>(idx, E, Xb);

    // input projection: Wx = Xb * Wb^T + bW   [2048 x 1024]
    dim3 g1(Mrows / 128, Dd / 128);
    gemm_bf16_kernel<<<g1, 256>>>(Xb, Wb, bW, Wx, Mrows, Dd, Dd);

    // recurrence (persistent, grid barrier)
    rnn_recurrence_kernel<<<RNN_BLOCKS, RNN_THREADS, RNN_SMEM>>>(Wx, U, bU, hsb);

    // output projection: logits = hsb * Woutb^T + bout   [2048 x 32000]
    dim3 g3(Mrows / 128, Vv / 128);
    gemm_bf16_kernel<<<g3, 256>>>(hsb, Woutb, bout, out, Mrows, Vv, Dd);

    // log_softmax
    lse_kernel<<<Mrows, 256>>>(out, lse);
    sub_lse_kernel<<<8192, 256>>>(out, lse, (Mrows * Vv) / 4);
}

// round 6
// speedup vs baseline: 1.0785x; 1.0785x over previous
#include <cuda_runtime.h>
#include <cuda_bf16.h>
#include <math.h>
#include <stdint.h>

// Problem dims (fixed)
#define Vv 32000
#define Dd 1024
#define Bb 8
#define Tt 256
#define Mrows (Bb * Tt)   // 2048

// ---------------- scratch (static device globals; allocation-free) ----------
__device__ __nv_bfloat16 g_Xb[Mrows * Dd];
__device__ __nv_bfloat16 g_Wb[Dd * Dd];
__device__ __nv_bfloat16 g_Woutb[(size_t)Vv * Dd];
__device__ float g_Wx[Mrows * Dd];
__device__ __nv_bfloat16 g_hsb[Mrows * Dd];
__device__ float g_h[2][Bb * Dd];

// grid barrier state
__device__ unsigned g_bar_count;
__device__ volatile unsigned g_bar_gen;

// ---------------- PTX helpers ----------------------------------------------
__device__ __forceinline__ uint32_t smem_u32(const void* p) {
    uint32_t a;
    asm("{ .reg .u64 t; cvta.to.shared.u64 t, %1; cvt.u32.u64 %0, t; }"
        : "=r"(a) : "l"(p));
    return a;
}

__device__ __forceinline__ void cp_async16(uint32_t dst, const void* src) {
    asm volatile("cp.async.cg.shared.global [%0], [%1], 16;" :: "r"(dst), "l"(src));
}
#define CP_COMMIT() asm volatile("cp.async.commit_group;" ::: "memory")
#define CP_WAIT(n)  asm volatile("cp.async.wait_group %0;" :: "n"(n) : "memory")

__device__ __forceinline__ void ldsm_x4(uint32_t& r0, uint32_t& r1,
                                        uint32_t& r2, uint32_t& r3, uint32_t addr) {
    asm volatile("ldmatrix.sync.aligned.m8n8.x4.shared.b16 {%0,%1,%2,%3}, [%4];"
                 : "=r"(r0), "=r"(r1), "=r"(r2), "=r"(r3) : "r"(addr));
}

__device__ __forceinline__ void mma16816(float& c0, float& c1, float& c2, float& c3,
                                         uint32_t a0, uint32_t a1, uint32_t a2, uint32_t a3,
                                         uint32_t b0, uint32_t b1) {
    asm volatile(
        "mma.sync.aligned.m16n8k16.row.col.f32.bf16.bf16.f32 "
        "{%0,%1,%2,%3}, {%4,%5,%6,%7}, {%8,%9}, {%0,%1,%2,%3};\n"
        : "+f"(c0), "+f"(c1), "+f"(c2), "+f"(c3)
        : "r"(a0), "r"(a1), "r"(a2), "r"(a3), "r"(b0), "r"(b1));
}

// ---------------- small helpers --------------------------------------------
__global__ void f32_to_bf16_kernel(const float4* __restrict__ src,
                                   __nv_bfloat162* __restrict__ dst, int n4) {
    for (int i = blockIdx.x * blockDim.x + threadIdx.x; i < n4;
         i += gridDim.x * blockDim.x) {
        float4 v = src[i];
        dst[2 * i]     = __floats2bfloat162_rn(v.x, v.y);
        dst[2 * i + 1] = __floats2bfloat162_rn(v.z, v.w);
    }
}

__global__ void gather_embed_kernel(const int* __restrict__ idx,
                                    const float* __restrict__ E,
                                    __nv_bfloat16* __restrict__ Xb) {
    int row = blockIdx.x;
    int v = idx[row];
    const float4* src = (const float4*)(E + (size_t)v * Dd);
    __nv_bfloat162* dst = (__nv_bfloat162*)(Xb + (size_t)row * Dd);
    for (int i = threadIdx.x; i < Dd / 4; i += blockDim.x) {
        float4 a = src[i];
        dst[2 * i]     = __floats2bfloat162_rn(a.x, a.y);
        dst[2 * i + 1] = __floats2bfloat162_rn(a.z, a.w);
    }
}

// ---------------- pipelined HMMA GEMM:  C[M,N] = A[M,K]*B[N,K]^T + bias[N] --
// BM=BN=128, BK=32, 256 threads (8 warps = 2m x 4n), warp tile 64x32.
// 3-stage cp.async pipeline, ldmatrix fragment loads, 2 CTAs/SM.
#define ROWB 80                    // 32 bf16 cols + 8 pad = 80 bytes per row
#define A_BYTES (128 * ROWB)       // 10240
#define STG (2 * A_BYTES)          // A + B per stage = 20480
#define S_ST 3
#define GEMM_SMEM (S_ST * STG + 128)

__device__ __forceinline__ void load_stage(const __nv_bfloat16* Ag,
                                           const __nv_bfloat16* Bg, int K,
                                           int kt, uint32_t base, int tid) {
    const int kbase = kt * 32;
#pragma unroll
    for (int i = 0; i < 2; i++) {
        int id = tid + i * 256;            // 0..511
        int row = id >> 2, seg = id & 3;   // 4 x 16B chunks per 64B row
        uint32_t soff = row * ROWB + seg * 16;
        cp_async16(base + soff, Ag + (size_t)row * K + kbase + seg * 8);
        cp_async16(base + A_BYTES + soff, Bg + (size_t)row * K + kbase + seg * 8);
    }
}

__global__ __launch_bounds__(256, 2)
void gemm_bf16_kernel(const __nv_bfloat16* __restrict__ A,
                      const __nv_bfloat16* __restrict__ Bm,
                      const float* __restrict__ bias,
                      float* __restrict__ C, int M, int N, int K) {
    extern __shared__ char dsm[];
    uint32_t sb = (smem_u32(dsm) + 127) & ~127u;

    const int tid = threadIdx.x;
    const int warp = tid >> 5, lane = tid & 31;
    const int wm = warp >> 2, wn = warp & 3;
    const int bm = blockIdx.x, bn = blockIdx.y;
    const int NT = K / 32;

    // per-lane ldmatrix address offsets (bytes)
    const uint32_t aLane = (uint32_t)((lane & 15) * ROWB + ((lane >> 4) << 4));
    const uint32_t bLane = (uint32_t)((((lane >> 4) << 3) + (lane & 7)) * ROWB +
                                      (((lane >> 3) & 1) << 4));

    float acc[4][4][4];
#pragma unroll
    for (int mi = 0; mi < 4; mi++)
#pragma unroll
        for (int ni = 0; ni < 4; ni++)
#pragma unroll
            for (int q = 0; q < 4; q++) acc[mi][ni][q] = 0.f;

    const __nv_bfloat16* Ag = A + (size_t)(bm * 128) * K;
    const __nv_bfloat16* Bg = Bm + (size_t)(bn * 128) * K;

    // prologue: stages 0,1
    load_stage(Ag, Bg, K, 0, sb, tid);
    CP_COMMIT();
    load_stage(Ag, Bg, K, 1, sb + STG, tid);
    CP_COMMIT();

    for (int kt = 0; kt < NT; kt++) {
        CP_WAIT(1);                 // stage kt resident
        __syncthreads();            // all warps done with buffer (kt-1)%3

        const int ktn = kt + 2;     // prefetch into (kt-1)%3 buffer
        if (ktn < NT)
            load_stage(Ag, Bg, K, ktn, sb + (ktn % S_ST) * STG, tid);
        CP_COMMIT();                // always commit (empty ok) to keep count

        const uint32_t stage = sb + (kt % S_ST) * STG;
        const uint32_t aBase = stage + (wm * 64) * ROWB + aLane;
        const uint32_t bBase = stage + A_BYTES + (wn * 32) * ROWB + bLane;

#pragma unroll
        for (int ks = 0; ks < 64; ks += 32) {   // two k16 steps (byte offset)
            uint32_t af[4][4], bf[2][4];
#pragma unroll
            for (int mi = 0; mi < 4; mi++)
                ldsm_x4(af[mi][0], af[mi][1], af[mi][2], af[mi][3],
                        aBase + mi * 16 * ROWB + ks);
#pragma unroll
            for (int nb = 0; nb < 2; nb++)
                ldsm_x4(bf[nb][0], bf[nb][1], bf[nb][2], bf[nb][3],
                        bBase + nb * 16 * ROWB + ks);
#pragma unroll
            for (int mi = 0; mi < 4; mi++)
#pragma unroll
                for (int nj = 0; nj < 4; nj++)
                    mma16816(acc[mi][nj][0], acc[mi][nj][1],
                             acc[mi][nj][2], acc[mi][nj][3],
                             af[mi][0], af[mi][1], af[mi][2], af[mi][3],
                             bf[nj >> 1][(nj & 1) * 2], bf[nj >> 1][(nj & 1) * 2 + 1]);
        }
    }

    // epilogue: + bias, float2 stores
    const int g = lane >> 2, tq = lane & 3;
#pragma unroll
    for (int ni = 0; ni < 4; ni++) {
        int col = bn * 128 + wn * 32 + ni * 8 + tq * 2;
        float b0 = bias[col], b1 = bias[col + 1];
#pragma unroll
        for (int mi = 0; mi < 4; mi++) {
            int row = bm * 128 + wm * 64 + mi * 16 + g;
            *(float2*)&C[(size_t)row * N + col] =
                make_float2(acc[mi][ni][0] + b0, acc[mi][ni][1] + b1);
            *(float2*)&C[(size_t)(row + 8) * N + col] =
                make_float2(acc[mi][ni][2] + b0, acc[mi][ni][3] + b1);
        }
    }
}

// ---------------- persistent RNN recurrence ---------------------------------
#define RNN_BLOCKS 128
#define RNN_THREADS 128
#define PADROW 1028
#define RNN_SMEM (2 * 8 * PADROW * 4)

__device__ __forceinline__ void grid_bar() {
    __syncthreads();
    if (threadIdx.x == 0) {
        unsigned gen = g_bar_gen;
        __threadfence();
        unsigned t = atomicAdd(&g_bar_count, 1u);
        if (t == RNN_BLOCKS - 1) {
            atomicExch(&g_bar_count, 0u);
            __threadfence();
            g_bar_gen = gen + 1;
        } else {
            while (g_bar_gen == gen) { }
        }
    }
    __syncthreads();
}

__global__ __launch_bounds__(RNN_THREADS)
void rnn_recurrence_kernel(const float* __restrict__ Wx,
                           const float* __restrict__ U,
                           const float* __restrict__ bU,
                           __nv_bfloat16* __restrict__ hsb) {
    extern __shared__ float sm[];
    float* Usm = sm;
    float* hsm = sm + 8 * PADROW;

    const int tid = threadIdx.x;
    const int lane = tid & 31, w = tid >> 5;
    const int rb = blockIdx.x * 8;

    for (int i = tid; i < 8 * 256; i += RNN_THREADS) {
        int lr = i >> 8, kc = i & 255;
        float4 u = *(const float4*)(U + (size_t)(rb + lr) * Dd + kc * 4);
        *(float4*)&Usm[lr * PADROW + kc * 4] = u;
    }

    int gid = blockIdx.x * RNN_THREADS + tid;
    if (gid < Bb * Dd) __stcg(&g_h[0][gid], 0.f);
    grid_bar();

    for (int t = 0; t < Tt; t++) {
        const float* hc = g_h[t & 1];
        for (int i = tid; i < 2048; i += RNN_THREADS) {
            float4 v = __ldcg((const float4*)hc + i);
            int b = i >> 8, kc = i & 255;
            *(float4*)&hsm[b * PADROW + kc * 4] = v;
        }
        __syncthreads();

        float acc[2][8];
#pragma unroll
        for (int r = 0; r < 2; r++)
#pragma unroll
            for (int b = 0; b < 8; b++) acc[r][b] = 0.f;

#pragma unroll
        for (int i = 0; i < 8; i++) {
            int k0 = lane * 4 + i * 128;
            float4 u0 = *(const float4*)&Usm[(w * 2) * PADROW + k0];
            float4 u1 = *(const float4*)&Usm[(w * 2 + 1) * PADROW + k0];
#pragma unroll
            for (int b = 0; b < 8; b++) {
                float4 h4 = *(const float4*)&hsm[b * PADROW + k0];
                acc[0][b] += u0.x * h4.x + u0.y * h4.y + u0.z * h4.z + u0.w * h4.w;
                acc[1][b] += u1.x * h4.x + u1.y * h4.y + u1.z * h4.z + u1.w * h4.w;
            }
        }

        float myval = 0.f;
#pragma unroll
        for (int j = 0; j < 16; j++) {
            float v = acc[j >> 3][j & 7];
            v += __shfl_xor_sync(0xffffffffu, v, 16);
            v += __shfl_xor_sync(0xffffffffu, v, 8);
            v += __shfl_xor_sync(0xffffffffu, v, 4);
            v += __shfl_xor_sync(0xffffffffu, v, 2);
            v += __shfl_xor_sync(0xffffffffu, v, 1);
            if (lane == j) myval = v;
        }

        if (lane < 16) {
            int rr = lane >> 3, b = lane & 7;
            int row = rb + w * 2 + rr;
            size_t wxi = ((size_t)b * Tt + t) * Dd + row;
            float x = myval + Wx[wxi] + bU[row];
            float hn = tanhf(x);
            __stcg(&g_h[(t & 1) ^ 1][b * Dd + row], hn);
            hsb[wxi] = __float2bfloat16(hn);
        }
        grid_bar();
    }
}

// ---------------- fused log-softmax (SMEM-resident row) ---------------------
#define LSM_SMEM (Vv * 4)   // 128000 bytes

__global__ __launch_bounds__(256)
void logsoftmax_kernel(float* __restrict__ C) {
    extern __shared__ float rowbuf[];
    __shared__ float red[256];
    const int row = blockIdx.x, tid = threadIdx.x;
    float4* p4 = (float4*)(C + (size_t)row * Vv);
    float4* r4 = (float4*)rowbuf;

    float m = -1e30f;
    for (int i = tid; i < Vv / 4; i += 256) {
        float4 v = p4[i];
        r4[i] = v;
        m = fmaxf(m, fmaxf(fmaxf(v.x, v.y), fmaxf(v.z, v.w)));
    }
    red[tid] = m; __syncthreads();
    for (int s = 128; s > 0; s >>= 1) {
        if (tid < s) red[tid] = fmaxf(red[tid], red[tid + s]);
        __syncthreads();
    }
    m = red[0]; __syncthreads();

    float sum = 0.f;
    for (int i = tid; i < Vv / 4; i += 256) {
        float4 v = r4[i];
        sum += expf(v.x - m) + expf(v.y - m) + expf(v.z - m) + expf(v.w - m);
    }
    red[tid] = sum; __syncthreads();
    for (int s = 128; s > 0; s >>= 1) {
        if (tid < s) red[tid] += red[tid + s];
        __syncthreads();
    }
    float lse = m + logf(red[0]);
    __syncthreads();

    for (int i = tid; i < Vv / 4; i += 256) {
        float4 v = r4[i];
        v.x -= lse; v.y -= lse; v.z -= lse; v.w -= lse;
        p4[i] = v;
    }
}

// ---------------- launcher ---------------------------------------------------
extern "C" void kernel_launch(void* const* d_in, const int* in_sizes, int n_in,
                              void* d_out, int out_size) {
    const int*   idx  = (const int*)d_in[0];
    const float* E    = (const float*)d_in[1];
    const float* W    = (const float*)d_in[2];
    const float* bW   = (const float*)d_in[3];
    const float* U    = (const float*)d_in[4];
    const float* bU   = (const float*)d_in[5];
    const float* Wout = (const float*)d_in[6];
    const float* bout = (const float*)d_in[7];
    float* out = (float*)d_out;

    void* p;
    cudaGetSymbolAddress(&p, g_Xb);    __nv_bfloat16* Xb    = (__nv_bfloat16*)p;
    cudaGetSymbolAddress(&p, g_Wb);    __nv_bfloat16* Wb    = (__nv_bfloat16*)p;
    cudaGetSymbolAddress(&p, g_Woutb); __nv_bfloat16* Woutb = (__nv_bfloat16*)p;
    cudaGetSymbolAddress(&p, g_Wx);    float*         Wx    = (float*)p;
    cudaGetSymbolAddress(&p, g_hsb);   __nv_bfloat16* hsb   = (__nv_bfloat16*)p;

    cudaFuncSetAttribute(rnn_recurrence_kernel,
                         cudaFuncAttributeMaxDynamicSharedMemorySize, RNN_SMEM);
    cudaFuncSetAttribute(gemm_bf16_kernel,
                         cudaFuncAttributeMaxDynamicSharedMemorySize, GEMM_SMEM);
    cudaFuncSetAttribute(logsoftmax_kernel,
                         cudaFuncAttributeMaxDynamicSharedMemorySize, LSM_SMEM);

    // weight conversions
    f32_to_bf16_kernel<<<512, 256>>>((const float4*)W,
                                     (__nv_bfloat162*)Wb, (Dd * Dd) / 4);
    f32_to_bf16_kernel<<<4096, 256>>>((const float4*)Wout,
                                      (__nv_bfloat162*)Woutb, (Vv * Dd) / 4);
    // embedding gather -> bf16
    gather_embed_kernel<<<Mrows, 128>>>(idx, E, Xb);

    // input projection: Wx = Xb * Wb^T + bW   [2048 x 1024]
    dim3 g1(Mrows / 128, Dd / 128);
    gemm_bf16_kernel<<<g1, 256, GEMM_SMEM>>>(Xb, Wb, bW, Wx, Mrows, Dd, Dd);

    // recurrence (persistent, grid barrier)
    rnn_recurrence_kernel<<<RNN_BLOCKS, RNN_THREADS, RNN_SMEM>>>(Wx, U, bU, hsb);

    // output projection: logits = hsb * Woutb^T + bout   [2048 x 32000]
    dim3 g3(Mrows / 128, Vv / 128);
    gemm_bf16_kernel<<<g3, 256, GEMM_SMEM>>>(hsb, Woutb, bout, out, Mrows, Vv, Dd);

    // fused log_softmax
    logsoftmax_kernel<<<Mrows, 256, LSM_SMEM>>>(out);
}

// round 7
// speedup vs baseline: 1.0862x; 1.0071x over previous
#include <cuda_runtime.h>
#include <cuda_bf16.h>
#include <math.h>
#include <stdint.h>

// Problem dims (fixed)
#define Vv 32000
#define Dd 1024
#define Bb 8
#define Tt 256
#define Mrows (Bb * Tt)   // 2048

// ---------------- scratch (static device globals; allocation-free) ----------
__device__ __nv_bfloat16 g_Xb[Mrows * Dd];
__device__ __nv_bfloat16 g_Wb[Dd * Dd];
__device__ __nv_bfloat16 g_Woutb[(size_t)Vv * Dd];
__device__ float g_Wx[Mrows * Dd];
__device__ __nv_bfloat16 g_hsb[Mrows * Dd];
__device__ float g_h[2][Bb * Dd];

#define RNN_CTAS 128
__device__ unsigned g_flags[RNN_CTAS * 8];   // 32B stride per flag

// ---------------- PTX helpers ----------------------------------------------
__device__ __forceinline__ uint32_t smem_u32(const void* p) {
    uint32_t a;
    asm("{ .reg .u64 t; cvta.to.shared.u64 t, %1; cvt.u32.u64 %0, t; }"
        : "=r"(a) : "l"(p));
    return a;
}

__device__ __forceinline__ void cp_async16(uint32_t dst, const void* src) {
    asm volatile("cp.async.cg.shared.global [%0], [%1], 16;" :: "r"(dst), "l"(src));
}
#define CP_COMMIT() asm volatile("cp.async.commit_group;" ::: "memory")
#define CP_WAIT(n)  asm volatile("cp.async.wait_group %0;" :: "n"(n) : "memory")

__device__ __forceinline__ void ldsm_x4(uint32_t& r0, uint32_t& r1,
                                        uint32_t& r2, uint32_t& r3, uint32_t addr) {
    asm volatile("ldmatrix.sync.aligned.m8n8.x4.shared.b16 {%0,%1,%2,%3}, [%4];"
                 : "=r"(r0), "=r"(r1), "=r"(r2), "=r"(r3) : "r"(addr));
}

__device__ __forceinline__ void mma16816(float& c0, float& c1, float& c2, float& c3,
                                         uint32_t a0, uint32_t a1, uint32_t a2, uint32_t a3,
                                         uint32_t b0, uint32_t b1) {
    asm volatile(
        "mma.sync.aligned.m16n8k16.row.col.f32.bf16.bf16.f32 "
        "{%0,%1,%2,%3}, {%4,%5,%6,%7}, {%8,%9}, {%0,%1,%2,%3};\n"
        : "+f"(c0), "+f"(c1), "+f"(c2), "+f"(c3)
        : "r"(a0), "r"(a1), "r"(a2), "r"(a3), "r"(b0), "r"(b1));
}

__device__ __forceinline__ unsigned ld_acquire(const unsigned* p) {
    unsigned v;
    asm volatile("ld.global.acquire.gpu.b32 %0, [%1];" : "=r"(v) : "l"(p) : "memory");
    return v;
}
__device__ __forceinline__ void st_release(unsigned* p, unsigned v) {
    asm volatile("st.global.release.gpu.b32 [%0], %1;" :: "l"(p), "r"(v) : "memory");
}

// ---------------- small helpers --------------------------------------------
__global__ void f32_to_bf16_kernel(const float4* __restrict__ src,
                                   __nv_bfloat162* __restrict__ dst, int n4) {
    for (int i = blockIdx.x * blockDim.x + threadIdx.x; i < n4;
         i += gridDim.x * blockDim.x) {
        float4 v = src[i];
        dst[2 * i]     = __floats2bfloat162_rn(v.x, v.y);
        dst[2 * i + 1] = __floats2bfloat162_rn(v.z, v.w);
    }
}

__global__ void gather_embed_kernel(const int* __restrict__ idx,
                                    const float* __restrict__ E,
                                    __nv_bfloat16* __restrict__ Xb) {
    int row = blockIdx.x;
    int v = idx[row];
    const float4* src = (const float4*)(E + (size_t)v * Dd);
    __nv_bfloat162* dst = (__nv_bfloat162*)(Xb + (size_t)row * Dd);
    for (int i = threadIdx.x; i < Dd / 4; i += blockDim.x) {
        float4 a = src[i];
        dst[2 * i]     = __floats2bfloat162_rn(a.x, a.y);
        dst[2 * i + 1] = __floats2bfloat162_rn(a.z, a.w);
    }
}

__global__ void rnn_reset_kernel() {
    int i = blockIdx.x * blockDim.x + threadIdx.x;
    if (i < Bb * Dd) g_h[0][i] = 0.f;
    if (i < RNN_CTAS) g_flags[i * 8] = 0u;
}

// ---------------- pipelined HMMA GEMM:  C[M,N] = A[M,K]*B[N,K]^T + bias[N] --
#define ROWB 80
#define A_BYTES (128 * ROWB)
#define STG (2 * A_BYTES)
#define S_ST 3
#define GEMM_SMEM (S_ST * STG + 128)

__device__ __forceinline__ void load_stage(const __nv_bfloat16* Ag,
                                           const __nv_bfloat16* Bg, int K,
                                           int kt, uint32_t base, int tid) {
    const int kbase = kt * 32;
#pragma unroll
    for (int i = 0; i < 2; i++) {
        int id = tid + i * 256;
        int row = id >> 2, seg = id & 3;
        uint32_t soff = row * ROWB + seg * 16;
        cp_async16(base + soff, Ag + (size_t)row * K + kbase + seg * 8);
        cp_async16(base + A_BYTES + soff, Bg + (size_t)row * K + kbase + seg * 8);
    }
}

__global__ __launch_bounds__(256, 2)
void gemm_bf16_kernel(const __nv_bfloat16* __restrict__ A,
                      const __nv_bfloat16* __restrict__ Bm,
                      const float* __restrict__ bias,
                      float* __restrict__ C, int M, int N, int K) {
    extern __shared__ char dsm[];
    uint32_t sb = (smem_u32(dsm) + 127) & ~127u;

    const int tid = threadIdx.x;
    const int warp = tid >> 5, lane = tid & 31;
    const int wm = warp >> 2, wn = warp & 3;
    const int bm = blockIdx.x, bn = blockIdx.y;
    const int NT = K / 32;

    const uint32_t aLane = (uint32_t)((lane & 15) * ROWB + ((lane >> 4) << 4));
    const uint32_t bLane = (uint32_t)((((lane >> 4) << 3) + (lane & 7)) * ROWB +
                                      (((lane >> 3) & 1) << 4));

    float acc[4][4][4];
#pragma unroll
    for (int mi = 0; mi < 4; mi++)
#pragma unroll
        for (int ni = 0; ni < 4; ni++)
#pragma unroll
            for (int q = 0; q < 4; q++) acc[mi][ni][q] = 0.f;

    const __nv_bfloat16* Ag = A + (size_t)(bm * 128) * K;
    const __nv_bfloat16* Bg = Bm + (size_t)(bn * 128) * K;

    load_stage(Ag, Bg, K, 0, sb, tid);
    CP_COMMIT();
    load_stage(Ag, Bg, K, 1, sb + STG, tid);
    CP_COMMIT();

    for (int kt = 0; kt < NT; kt++) {
        CP_WAIT(1);
        __syncthreads();

        const int ktn = kt + 2;
        if (ktn < NT)
            load_stage(Ag, Bg, K, ktn, sb + (ktn % S_ST) * STG, tid);
        CP_COMMIT();

        const uint32_t stage = sb + (kt % S_ST) * STG;
        const uint32_t aBase = stage + (wm * 64) * ROWB + aLane;
        const uint32_t bBase = stage + A_BYTES + (wn * 32) * ROWB + bLane;

#pragma unroll
        for (int ks = 0; ks < 64; ks += 32) {
            uint32_t af[4][4], bf[2][4];
#pragma unroll
            for (int mi = 0; mi < 4; mi++)
                ldsm_x4(af[mi][0], af[mi][1], af[mi][2], af[mi][3],
                        aBase + mi * 16 * ROWB + ks);
#pragma unroll
            for (int nb = 0; nb < 2; nb++)
                ldsm_x4(bf[nb][0], bf[nb][1], bf[nb][2], bf[nb][3],
                        bBase + nb * 16 * ROWB + ks);
#pragma unroll
            for (int mi = 0; mi < 4; mi++)
#pragma unroll
                for (int nj = 0; nj < 4; nj++)
                    mma16816(acc[mi][nj][0], acc[mi][nj][1],
                             acc[mi][nj][2], acc[mi][nj][3],
                             af[mi][0], af[mi][1], af[mi][2], af[mi][3],
                             bf[nj >> 1][(nj & 1) * 2], bf[nj >> 1][(nj & 1) * 2 + 1]);
        }
    }

    const int g = lane >> 2, tq = lane & 3;
#pragma unroll
    for (int ni = 0; ni < 4; ni++) {
        int col = bn * 128 + wn * 32 + ni * 8 + tq * 2;
        float b0 = bias[col], b1 = bias[col + 1];
#pragma unroll
        for (int mi = 0; mi < 4; mi++) {
            int row = bm * 128 + wm * 64 + mi * 16 + g;
            *(float2*)&C[(size_t)row * N + col] =
                make_float2(acc[mi][ni][0] + b0, acc[mi][ni][1] + b1);
            *(float2*)&C[(size_t)(row + 8) * N + col] =
                make_float2(acc[mi][ni][2] + b0, acc[mi][ni][3] + b1);
        }
    }
}

// ---------------- persistent RNN recurrence (flag handshake, no atomics) ----
// 128 CTAs x 256 threads. Warp w: rows rb+(w&3)*2 .. +1, batches (w>>2)*4 .. +3.
// U rows live in registers. h staged to SMEM each step. Per-CTA release flag;
// consumers poll 128 flags with 128 parallel threads.
__global__ __launch_bounds__(256)
void rnn_recurrence_kernel(const float* __restrict__ Wx,
                           const float* __restrict__ U,
                           const float* __restrict__ bU,
                           __nv_bfloat16* __restrict__ hsb) {
    __shared__ float hsm[8][1024];

    const int tid = threadIdx.x;
    const int lane = tid & 31, w = tid >> 5;
    const int rb = blockIdx.x * 8;
    const int r0 = rb + (w & 3) * 2;      // first of this warp's 2 rows
    const int bbase = (w >> 2) * 4;       // first of this warp's 4 batches

    // hoist 2 rows of U into registers (64 floats)
    float4 u0[8], u1[8];
#pragma unroll
    for (int i = 0; i < 8; i++) {
        u0[i] = *(const float4*)(U + (size_t)r0 * Dd + lane * 4 + i * 128);
        u1[i] = *(const float4*)(U + (size_t)(r0 + 1) * Dd + lane * 4 + i * 128);
    }
    // per-output-lane constants
    const int orow = r0 + (lane >> 2);        // lanes 0..7: output row
    const int obat = bbase + (lane & 3);      // lanes 0..7: output batch
    const float bUv = (lane < 8) ? __ldg(&bU[orow]) : 0.f;

    for (int t = 0; t < Tt; t++) {
        // wait for all producers of h(t): flags >= t (parallel poll)
        if (t > 0 && tid < RNN_CTAS) {
            while (ld_acquire(&g_flags[tid * 8]) < (unsigned)t) { }
        }
        __syncthreads();

        // prefetch Wx + stage h(t) into SMEM
        float wxv = 0.f;
        if (lane < 8)
            wxv = __ldg(&Wx[((size_t)obat * Tt + t) * Dd + orow]);

        const float4* hc = (const float4*)g_h[t & 1];
        for (int i = tid; i < 2048; i += 256) {
            float4 v = __ldcg(hc + i);
            *(float4*)&hsm[i >> 8][(i & 255) * 4] = v;
        }
        __syncthreads();

        float acc[2][4];
#pragma unroll
        for (int r = 0; r < 2; r++)
#pragma unroll
            for (int b = 0; b < 4; b++) acc[r][b] = 0.f;

#pragma unroll
        for (int i = 0; i < 8; i++) {
            const int k0 = lane * 4 + i * 128;
#pragma unroll
            for (int b = 0; b < 4; b++) {
                float4 h4 = *(const float4*)&hsm[bbase + b][k0];
                acc[0][b] += u0[i].x * h4.x + u0[i].y * h4.y +
                             u0[i].z * h4.z + u0[i].w * h4.w;
                acc[1][b] += u1[i].x * h4.x + u1[i].y * h4.y +
                             u1[i].z * h4.z + u1[i].w * h4.w;
            }
        }

        // butterfly-reduce 8 outputs; output j -> lane j (j = rr*4 + bb)
        float myval = 0.f;
#pragma unroll
        for (int j = 0; j < 8; j++) {
            float v = acc[j >> 2][j & 3];
            v += __shfl_xor_sync(0xffffffffu, v, 16);
            v += __shfl_xor_sync(0xffffffffu, v, 8);
            v += __shfl_xor_sync(0xffffffffu, v, 4);
            v += __shfl_xor_sync(0xffffffffu, v, 2);
            v += __shfl_xor_sync(0xffffffffu, v, 1);
            if (lane == j) myval = v;
        }

        if (lane < 8) {
            float x = myval + wxv + bUv;
            float hn = tanhf(x);
            __stcg(&g_h[(t + 1) & 1][obat * Dd + orow], hn);
            hsb[((size_t)obat * Tt + t) * Dd + orow] = __float2bfloat16(hn);
            __threadfence();
        }
        __syncthreads();
        if (tid == 0) st_release(&g_flags[blockIdx.x * 8], (unsigned)(t + 1));
    }
}

// ---------------- fused log-softmax (SMEM-resident row) ---------------------
#define LSM_SMEM (Vv * 4)   // 128000 bytes

__global__ __launch_bounds__(256)
void logsoftmax_kernel(float* __restrict__ C) {
    extern __shared__ float rowbuf[];
    __shared__ float red[256];
    const int row = blockIdx.x, tid = threadIdx.x;
    float4* p4 = (float4*)(C + (size_t)row * Vv);
    float4* r4 = (float4*)rowbuf;

    float m = -1e30f;
    for (int i = tid; i < Vv / 4; i += 256) {
        float4 v = p4[i];
        r4[i] = v;
        m = fmaxf(m, fmaxf(fmaxf(v.x, v.y), fmaxf(v.z, v.w)));
    }
    red[tid] = m; __syncthreads();
    for (int s = 128; s > 0; s >>= 1) {
        if (tid < s) red[tid] = fmaxf(red[tid], red[tid + s]);
        __syncthreads();
    }
    m = red[0]; __syncthreads();

    float sum = 0.f;
    for (int i = tid; i < Vv / 4; i += 256) {
        float4 v = r4[i];
        sum += expf(v.x - m) + expf(v.y - m) + expf(v.z - m) + expf(v.w - m);
    }
    red[tid] = sum; __syncthreads();
    for (int s = 128; s > 0; s >>= 1) {
        if (tid < s) red[tid] += red[tid + s];
        __syncthreads();
    }
    float lse = m + logf(red[0]);
    __syncthreads();

    for (int i = tid; i < Vv / 4; i += 256) {
        float4 v = r4[i];
        v.x -= lse; v.y -= lse; v.z -= lse; v.w -= lse;
        p4[i] = v;
    }
}

// ---------------- launcher ---------------------------------------------------
extern "C" void kernel_launch(void* const* d_in, const int* in_sizes, int n_in,
                              void* d_out, int out_size) {
    const int*   idx  = (const int*)d_in[0];
    const float* E    = (const float*)d_in[1];
    const float* W    = (const float*)d_in[2];
    const float* bW   = (const float*)d_in[3];
    const float* U    = (const float*)d_in[4];
    const float* bU   = (const float*)d_in[5];
    const float* Wout = (const float*)d_in[6];
    const float* bout = (const float*)d_in[7];
    float* out = (float*)d_out;

    void* p;
    cudaGetSymbolAddress(&p, g_Xb);    __nv_bfloat16* Xb    = (__nv_bfloat16*)p;
    cudaGetSymbolAddress(&p, g_Wb);    __nv_bfloat16* Wb    = (__nv_bfloat16*)p;
    cudaGetSymbolAddress(&p, g_Woutb); __nv_bfloat16* Woutb = (__nv_bfloat16*)p;
    cudaGetSymbolAddress(&p, g_Wx);    float*         Wx    = (float*)p;
    cudaGetSymbolAddress(&p, g_hsb);   __nv_bfloat16* hsb   = (__nv_bfloat16*)p;

    cudaFuncSetAttribute(gemm_bf16_kernel,
                         cudaFuncAttributeMaxDynamicSharedMemorySize, GEMM_SMEM);
    cudaFuncSetAttribute(logsoftmax_kernel,
                         cudaFuncAttributeMaxDynamicSharedMemorySize, LSM_SMEM);

    // weight conversions
    f32_to_bf16_kernel<<<512, 256>>>((const float4*)W,
                                     (__nv_bfloat162*)Wb, (Dd * Dd) / 4);
    f32_to_bf16_kernel<<<4096, 256>>>((const float4*)Wout,
                                      (__nv_bfloat162*)Woutb, (Vv * Dd) / 4);
    // embedding gather -> bf16 ; reset rnn state
    gather_embed_kernel<<<Mrows, 128>>>(idx, E, Xb);
    rnn_reset_kernel<<<32, 256>>>();

    // input projection: Wx = Xb * Wb^T + bW   [2048 x 1024]
    dim3 g1(Mrows / 128, Dd / 128);
    gemm_bf16_kernel<<<g1, 256, GEMM_SMEM>>>(Xb, Wb, bW, Wx, Mrows, Dd, Dd);

    // recurrence (persistent, per-CTA flag handshake)
    rnn_recurrence_kernel<<<RNN_CTAS, 256>>>(Wx, U, bU, hsb);

    // output projection: logits = hsb * Woutb^T + bout   [2048 x 32000]
    dim3 g3(Mrows / 128, Vv / 128);
    gemm_bf16_kernel<<<g3, 256, GEMM_SMEM>>>(hsb, Woutb, bout, out, Mrows, Vv, Dd);

    // fused log_softmax
    logsoftmax_kernel<<<Mrows, 256, LSM_SMEM>>>(out);
}